// round 13
// baseline (speedup 1.0000x reference)
#include <cuda_runtime.h>
#include <math.h>

#define Bsz   64
#define Tlen  512
#define Edim  512
#define Hdim  512
#define NCTA  128          // seq CTAs (8 groups of 16)
#define NPROD 24           // producer CTAs (work-stealing; extras harmless)
#define TPB   128
// smem: Wa 32*512 + Wb 32*1024 + hbuf 8*1024 floats = 224 KB
#define SMEM_FLOATS (32*512 + 32*1024 + 8*1024)
#define SMEM_BYTES  (SMEM_FLOATS * 4)

__device__ float g_pre0[(size_t)Tlen * Bsz * Hdim];   // [t][b][h]
__device__ float g_h0[2][Bsz][Hdim];
__device__ float g_h1[2][Bsz][Hdim];
__device__ unsigned int g_cnt[8 * 32];      // per-group barrier counters
__device__ unsigned int g_tready[Tlen];     // per-t: #ncol blocks done (0..8)
__device__ unsigned int g_work;             // producer work counter

// ---------------------------------------------------------------------------
// primitives
// ---------------------------------------------------------------------------
__device__ __forceinline__ void atom_add_release_gpu(unsigned* p, unsigned v) {
    unsigned old;
    asm volatile("atom.add.release.gpu.u32 %0, [%1], %2;"
                 : "=r"(old) : "l"(p), "r"(v) : "memory");
}
__device__ __forceinline__ unsigned ld_acquire_gpu(const unsigned* p) {
    unsigned v;
    asm volatile("ld.acquire.gpu.u32 %0, [%1];" : "=r"(v) : "l"(p) : "memory");
    return v;
}
// packed fp32x2 FMA
__device__ __forceinline__ void F2(unsigned long long &d, unsigned long long a,
                                   unsigned long long b) {
    asm("fma.rn.f32x2 %0, %1, %2, %0;" : "+l"(d) : "l"(a), "l"(b));
}
__device__ __forceinline__ unsigned long long pk2(float x, float y) {
    unsigned long long p;
    asm("mov.b64 %0, {%1, %2};" : "=l"(p) : "f"(x), "f"(y));
    return p;
}
__device__ __forceinline__ float2 upk(unsigned long long v) {
    float2 r;
    asm("mov.b64 {%0, %1}, %2;" : "=f"(r.x), "=f"(r.y) : "l"(v));
    return r;
}

// ---------------------------------------------------------------------------
// Zero h-state + ALL counters (replay safety)
// ---------------------------------------------------------------------------
__global__ void zero_h_kernel() {
    int i = blockIdx.x * blockDim.x + threadIdx.x;
    if (i < 2 * Bsz * Hdim) {
        ((float*)g_h0)[i] = 0.0f;
        ((float*)g_h1)[i] = 0.0f;
    }
    if (i < Tlen) g_tready[i] = 0;
    if (i < 8 * 32) g_cnt[i] = 0;
    if (i == 0) g_work = 0;
}

// ---------------------------------------------------------------------------
// Producer CTA body: pre0[t][b][h] = emb[x[b,t]].W_ih0[h] + b_ih0[h] + b_hh0[h]
// 128 threads, tile 64m x 64n. Work-stealing in t-major order; per-t ready
// counter released after stores. Dead batches (len_b <= t) skip FMA + stores.
// Register double-buffered global loads (1 CTA/SM -> must self-hide latency).
// Same accumulation order/pairing as the R5 pre0 kernel (bitwise identical).
// ---------------------------------------------------------------------------
__device__ void producer_cta(
    const int*   __restrict__ x,
    const float* __restrict__ emb,
    const float* __restrict__ Wih,
    const float* __restrict__ bih,
    const float* __restrict__ bhh,
    const int*   __restrict__ lengths,
    float* smem)
{
    unsigned long long* As2 = (unsigned long long*)smem;     // [8][64]
    unsigned long long* Bs2 = As2 + 8 * 64;                  // [8][64]
    int* tok = (int*)(Bs2 + 8 * 64);                         // [64]
    __shared__ int s_idx, s_nb;

    const int tid  = threadIdx.x;
    const int mm   = tid & 63;
    const int half = tid >> 6;                 // 0..1 -> kq pair {2h, 2h+1}
    const int pm   = mm ^ (((mm >> 4) & 1) << 1);
    const int k0   = half * 8;                 // float offset of this half's 8 k

    const int ty = tid >> 4;                   // 0..7
    const int tx = tid & 15;                   // 0..15
    const int mA = ty * 4;                     // rows 0..28
    const int mB = ty * 4 + 32;                // rows 32..60
    const int xaA = ((mA >> 4) & 1) << 1;
    const int xaB = ((mB >> 4) & 1) << 1;
    const int caA0 = mA ^ xaA, caA2 = (mA + 2) ^ xaA;
    const int caB0 = mB ^ xaB, caB2 = (mB + 2) ^ xaB;
    const int xb  = ((tx >> 2) & 1) << 1;
    const int cb0 = (tx * 4) ^ xb, cb2 = (tx * 4 + 2) ^ xb;

    for (;;) {
        if (tid == 0) s_idx = (int)atomicAdd(&g_work, 1u);
        __syncthreads();
        const int idx = s_idx;
        if (idx >= Tlen * 8) break;
        const int t    = idx >> 3;
        const int ncol = (idx & 7) * 64;

        if (tid == 0) {            // nb = #batches with len > t (sorted desc)
            int lo = 0, hi = Bsz;
            while (lo < hi) {
                int mid = (lo + hi) >> 1;
                if (lengths[mid] > t) lo = mid + 1; else hi = mid;
            }
            s_nb = lo;
        }
        if (tid < 64) tok[tid] = x[tid * Tlen + t];
        __syncthreads();
        const int nb = s_nb;
        const bool aliveA = (mA < nb);
        const bool aliveB = (mB < nb);
        const bool ldA    = (mm < nb);

        unsigned long long accA[4][4], accB[4][4];
#pragma unroll
        for (int i = 0; i < 4; i++)
#pragma unroll
            for (int j = 0; j < 4; j++) { accA[i][j] = 0ull; accB[i][j] = 0ull; }

        const float* ar = emb + (size_t)tok[mm] * Edim;
        const float* wr = Wih + (size_t)(ncol + mm) * Edim;

        float4 va0, va1, wb0, wb1;
        if (ldA) { va0 = *(const float4*)(ar + k0);
                   va1 = *(const float4*)(ar + k0 + 4); }
        wb0 = *(const float4*)(wr + k0);
        wb1 = *(const float4*)(wr + k0 + 4);

        for (int kc = 0; kc < Edim; kc += 16) {
            __syncthreads();            // prior compute done reading smem
            if (ldA) {
                As2[(half*4+0)*64 + pm] = pk2(va0.x, va0.y);
                As2[(half*4+1)*64 + pm] = pk2(va0.z, va0.w);
                As2[(half*4+2)*64 + pm] = pk2(va1.x, va1.y);
                As2[(half*4+3)*64 + pm] = pk2(va1.z, va1.w);
            }
            Bs2[(half*4+0)*64 + pm] = pk2(wb0.x, wb0.y);
            Bs2[(half*4+1)*64 + pm] = pk2(wb0.z, wb0.w);
            Bs2[(half*4+2)*64 + pm] = pk2(wb1.x, wb1.y);
            Bs2[(half*4+3)*64 + pm] = pk2(wb1.z, wb1.w);
            __syncthreads();

            if (kc + 16 < Edim) {       // prefetch next chunk (hidden by compute)
                if (ldA) { va0 = *(const float4*)(ar + kc + 16 + k0);
                           va1 = *(const float4*)(ar + kc + 16 + k0 + 4); }
                wb0 = *(const float4*)(wr + kc + 16 + k0);
                wb1 = *(const float4*)(wr + kc + 16 + k0 + 4);
            }

#pragma unroll
            for (int kk2 = 0; kk2 < 8; kk2++) {
                ulonglong2 b01 = *(const ulonglong2*)&Bs2[kk2*64 + cb0];
                ulonglong2 b23 = *(const ulonglong2*)&Bs2[kk2*64 + cb2];
                unsigned long long bn[4] = {b01.x, b01.y, b23.x, b23.y};
                if (aliveA) {
                    ulonglong2 a01 = *(const ulonglong2*)&As2[kk2*64 + caA0];
                    ulonglong2 a23 = *(const ulonglong2*)&As2[kk2*64 + caA2];
                    unsigned long long am[4] = {a01.x, a01.y, a23.x, a23.y};
#pragma unroll
                    for (int i = 0; i < 4; i++)
#pragma unroll
                        for (int j = 0; j < 4; j++) F2(accA[i][j], am[i], bn[j]);
                }
                if (aliveB) {
                    ulonglong2 a01 = *(const ulonglong2*)&As2[kk2*64 + caB0];
                    ulonglong2 a23 = *(const ulonglong2*)&As2[kk2*64 + caB2];
                    unsigned long long am[4] = {a01.x, a01.y, a23.x, a23.y};
#pragma unroll
                    for (int i = 0; i < 4; i++)
#pragma unroll
                        for (int j = 0; j < 4; j++) F2(accB[i][j], am[i], bn[j]);
                }
            }
        }

        // epilogue: bias add + store alive rows
        const int nbase = ncol + tx * 4;
        float4 bias;
        bias.x = bih[nbase + 0] + bhh[nbase + 0];
        bias.y = bih[nbase + 1] + bhh[nbase + 1];
        bias.z = bih[nbase + 2] + bhh[nbase + 2];
        bias.w = bih[nbase + 3] + bhh[nbase + 3];
#pragma unroll
        for (int i = 0; i < 4; i++) {
            if (mA + i < nb) {
                float2 u0 = upk(accA[i][0]), u1 = upk(accA[i][1]);
                float2 u2 = upk(accA[i][2]), u3 = upk(accA[i][3]);
                float4 o;
                o.x = u0.x + u0.y + bias.x;  o.y = u1.x + u1.y + bias.y;
                o.z = u2.x + u2.y + bias.z;  o.w = u3.x + u3.y + bias.w;
                *(float4*)(g_pre0 + ((size_t)t * Bsz + mA + i) * Hdim + nbase) = o;
            }
            if (mB + i < nb) {
                float2 u0 = upk(accB[i][0]), u1 = upk(accB[i][1]);
                float2 u2 = upk(accB[i][2]), u3 = upk(accB[i][3]);
                float4 o;
                o.x = u0.x + u0.y + bias.x;  o.y = u1.x + u1.y + bias.y;
                o.z = u2.x + u2.y + bias.z;  o.w = u3.x + u3.y + bias.w;
                *(float4*)(g_pre0 + ((size_t)t * Bsz + mB + i) * Hdim + nbase) = o;
            }
        }
        __syncthreads();                 // all stores issued before release
        if (tid == 0) atom_add_release_gpu(&g_tready[t], 1u);
    }
}

// ---------------------------------------------------------------------------
// Per-group barrier + merged next-t readiness poll.
// ---------------------------------------------------------------------------
__device__ __forceinline__ void group_barrier_pre(int grp, unsigned need, int tnext) {
    __syncthreads();
    if (threadIdx.x == 0) {
        atom_add_release_gpu(&g_cnt[grp * 32], 1u);
        if (tnext >= 0)
            while (ld_acquire_gpu(&g_tready[tnext]) < 8u) { }
        while (ld_acquire_gpu(&g_cnt[grp * 32]) < need) { }
    }
    __syncthreads();
}

// f32x2 GEMM phase: 4b x 8h outputs/thread, K-sliced 16 ways.  (R5 exact)
template<int JCOUNT, int WSTRIDE>
__device__ __forceinline__ void phase_accum2(
    const float* __restrict__ hbuf, const float* __restrict__ W,
    int tb, int th, int ks, unsigned long long acc[4][8])
{
#pragma unroll
    for (int bi = 0; bi < 4; bi++)
#pragma unroll
        for (int hi = 0; hi < 8; hi++) acc[bi][hi] = 0ull;

#pragma unroll 4
    for (int j = 0; j < JCOUNT; j++) {
        const int k = ((j * 16 + ks) << 2);
        ulonglong2 a[4], w[8];
#pragma unroll
        for (int q = 0; q < 4; q++)
            a[q] = *(const ulonglong2*)(hbuf + (size_t)(tb + q) * 1024 + k);
#pragma unroll
        for (int q = 0; q < 8; q++)
            w[q] = *(const ulonglong2*)(W + (size_t)(th + q) * WSTRIDE + k);
#pragma unroll
        for (int bi = 0; bi < 4; bi++)
#pragma unroll
            for (int hi = 0; hi < 8; hi++) {
                F2(acc[bi][hi], a[bi].x, w[hi].x);
                F2(acc[bi][hi], a[bi].y, w[hi].y);
            }
    }
}

// 32 partials/lane -> 2 full sums/lane across the 16-lane segment. (R5 exact)
__device__ __forceinline__ void fold32to2(float v[32], int ks) {
    int cnt = 32;
#pragma unroll
    for (int m = 8; m >= 1; m >>= 1) {
        const bool hi = (ks & m) != 0;
        const int half = cnt >> 1;
#pragma unroll
        for (int j = 0; j < 16; j++) {
            if (j >= half) break;
            float send = hi ? v[j] : v[j + half];
            float recv = __shfl_xor_sync(0xffffffffu, send, m, 16);
            float keep = hi ? v[j + half] : v[j];
            v[j] = keep + recv;
        }
        cnt = half;
    }
}

// ---------------------------------------------------------------------------
// Fused persistent kernel: CTAs 0..127 = R5 seq loop; CTAs 128+ = producers.
// ---------------------------------------------------------------------------
__global__ void __launch_bounds__(TPB, 1) rnn_fused_kernel(
    const int*   __restrict__ x,
    const float* __restrict__ emb,
    const float* __restrict__ Wih,
    const float* __restrict__ Whh,
    const float* __restrict__ bih,
    const float* __restrict__ bhh,
    const int*   __restrict__ lengths,
    float*       __restrict__ out)
{
    extern __shared__ float smem_dyn[];

    if (blockIdx.x >= NCTA) {
        producer_cta(x, emb, Wih, bih, bhh, lengths, smem_dyn);
        return;
    }

    float* Wa   = smem_dyn;                 // 32 x 512
    float* Wb   = smem_dyn + 32 * 512;      // 32 x 1024
    float* hbuf = Wb + 32 * 1024;           // 8 x 1024 staging

    const int cta   = blockIdx.x;
    const int grp   = cta >> 4;
    const int bbase = grp * 8;
    const int hbase = (cta & 15) * 32;
    const int tid   = threadIdx.x;

    // resident weight slices
    {
        const float4* src = (const float4*)(Whh + (size_t)hbase * Hdim);
        float4* dst = (float4*)Wa;
        for (int i = tid; i < 32 * Hdim / 4; i += TPB) dst[i] = src[i];

        const float4* s1 = (const float4*)(Wih + (size_t)Hdim * Edim + (size_t)hbase * Edim);
        const float4* s2 = (const float4*)(Whh + (size_t)Hdim * Hdim + (size_t)hbase * Hdim);
        for (int i = tid; i < 32 * 512 / 4; i += TPB) {
            int r = i >> 7, c = i & 127;
            ((float4*)(Wb + (size_t)r * 1024))[c]       = s1[i];
            ((float4*)(Wb + (size_t)r * 1024 + 512))[c] = s2[i];
        }
    }

    // compute mapping (R5): warp halves share th, differ in tb
    const int ks = tid & 15;
    const int g  = tid >> 4;
    const int tb = (g & 1) * 4;
    const int th = (g >> 1) * 8;

    // epilogue ownership: lane ks owns outputs o=2ks, 2ks+1
    const int blo = tb + (ks >> 2);
    const int hlo = th + 2 * (ks & 3);
    const int b_o = bbase + blo;
    const int h_o = hbase + hlo;
    const int lenb = lengths[b_o];
    float2 bias1;
    bias1.x = bih[Hdim + h_o] + bhh[Hdim + h_o];
    bias1.y = bih[Hdim + h_o + 1] + bhh[Hdim + h_o + 1];

    // group horizon
    int smax = 1;
#pragma unroll
    for (int q = 0; q < 8; q++) {
        int l = lengths[bbase + q];
        smax = (l > smax) ? l : smax;
    }

    // phase-0 readiness: pre0[t=0] must be complete before any preval read
    if (tid == 0)
        while (ld_acquire_gpu(&g_tready[0]) < 8u) { }
    __syncthreads();

    float2 h0fin = make_float2(0.0f, 0.0f);
    float2 h1fin = make_float2(0.0f, 0.0f);

    for (int s = 0; s <= smax; ++s) {
        const int p = s & 1;

        // ---- stage h0_after[s-1] | h1_after[s-2] into smem ----
#pragma unroll
        for (int it = 0; it < 8; it++) {
            int i = tid + it * TPB;
            int r = i >> 7, c = (i & 127) << 2;
            float4 v0 = __ldcg((const float4*)&g_h0[p][bbase + r][c]);
            float4 v1 = __ldcg((const float4*)&g_h1[p][bbase + r][c]);
            *(float4*)(hbuf + (size_t)r * 1024 + c)       = v0;
            *(float4*)(hbuf + (size_t)r * 1024 + 512 + c) = v1;
        }
        // early pre0 load (hidden under GEMM; readiness guaranteed for s<smax;
        // at s==smax all rows are frozen and the value is discarded)
        float2 preval = make_float2(0.0f, 0.0f);
        if (s < Tlen)
            preval = __ldcs((const float2*)&g_pre0[((size_t)s * Bsz + b_o) * Hdim + h_o]);
        __syncthreads();

        unsigned long long acc2[4][8];
        float v[32];

        // ===== layer 0: h0_new = tanh(pre0 + h0 @ Whh0^T) =====
        if (s < Tlen) {
            phase_accum2<8, 512>(hbuf, Wa, tb, th, ks, acc2);
#pragma unroll
            for (int bi = 0; bi < 4; bi++)
#pragma unroll
                for (int hi = 0; hi < 8; hi++) {
                    float2 u = upk(acc2[bi][hi]);
                    v[bi * 8 + hi] = u.x + u.y;
                }
            fold32to2(v, ks);
            float s0 = v[0] + preval.x;
            float s1 = v[1] + preval.y;
            float2 hp = *(const float2*)&hbuf[(size_t)blo * 1024 + h_o];
            float2 hn;
            hn.x = (s < lenb) ? tanhf(s0) : hp.x;
            hn.y = (s < lenb) ? tanhf(s1) : hp.y;
            *(float2*)&g_h0[p ^ 1][b_o][h_o] = hn;
            h0fin = hn;
        }

        // ===== layer 1: h1_new = tanh([h0_new,h1] @ [Wih1|Whh1]^T + b1) =====
        if (s >= 1) {
            phase_accum2<16, 1024>(hbuf, Wb, tb, th, ks, acc2);
#pragma unroll
            for (int bi = 0; bi < 4; bi++)
#pragma unroll
                for (int hi = 0; hi < 8; hi++) {
                    float2 u = upk(acc2[bi][hi]);
                    v[bi * 8 + hi] = u.x + u.y;
                }
            fold32to2(v, ks);
            float s0 = v[0] + bias1.x;
            float s1 = v[1] + bias1.y;
            float2 hp = *(const float2*)&hbuf[(size_t)blo * 1024 + 512 + h_o];
            float2 hn;
            hn.x = ((s - 1) < lenb) ? tanhf(s0) : hp.x;
            hn.y = ((s - 1) < lenb) ? tanhf(s1) : hp.y;
            if (s < Tlen) *(float2*)&g_h1[p ^ 1][b_o][h_o] = hn;
            h1fin = hn;
        }

        if (s < smax)
            group_barrier_pre(grp, 16u * (unsigned)(s + 1),
                              (s + 1 < smax) ? (s + 1) : -1);
    }

    // outputs: [ h1_final (64x512) | hidden (64x2x512: layer0, layer1) ]
    *(float2*)&out[(size_t)b_o * Hdim + h_o] = h1fin;
    *(float2*)&out[(size_t)Bsz * Hdim + (size_t)b_o * 2 * Hdim + h_o] = h0fin;
    *(float2*)&out[(size_t)Bsz * Hdim + (size_t)b_o * 2 * Hdim + Hdim + h_o] = h1fin;
}

// ---------------------------------------------------------------------------
extern "C" void kernel_launch(void* const* d_in, const int* in_sizes, int n_in,
                              void* d_out, int out_size) {
    const int*   x       = (const int*)  d_in[0];
    const int*   lengths = (const int*)  d_in[1];
    const float* emb     = (const float*)d_in[2];
    const float* Wih     = (const float*)d_in[3];
    const float* Whh     = (const float*)d_in[4];
    const float* bih     = (const float*)d_in[5];
    const float* bhh     = (const float*)d_in[6];
    float* out = (float*)d_out;

    cudaFuncSetAttribute(rnn_fused_kernel,
                         cudaFuncAttributeMaxDynamicSharedMemorySize, SMEM_BYTES);

    zero_h_kernel<<<(2 * Bsz * Hdim + 255) / 256, 256>>>();

    rnn_fused_kernel<<<NCTA + NPROD, TPB, SMEM_BYTES>>>(
        x, emb, Wih, Whh, bih, bhh, lengths, out);
}

// round 14
// speedup vs baseline: 2.0041x; 2.0041x over previous
#include <cuda_runtime.h>
#include <math.h>

#define Bsz   64
#define Tlen  512
#define Edim  512
#define Hdim  512
#define NCTA  128
#define TPB   128
// smem: Wa 32*512 + Wb 32*1024 + hbuf 8*1024 floats = 224 KB
#define SMEM_FLOATS (32*512 + 32*1024 + 8*1024)
#define SMEM_BYTES  (SMEM_FLOATS * 4)

__device__ float g_pre0[(size_t)Tlen * Bsz * Hdim];   // [t][b][h]
__device__ float g_h0[2][Bsz][Hdim];
__device__ float g_h1[2][Bsz][Hdim];
__device__ unsigned int g_cnt[8 * 32];   // per-group monotonic barrier counter

// ---------------------------------------------------------------------------
// primitives
// ---------------------------------------------------------------------------
__device__ __forceinline__ void atom_add_release_gpu(unsigned* p, unsigned v) {
    unsigned old;
    asm volatile("atom.add.release.gpu.u32 %0, [%1], %2;"
                 : "=r"(old) : "l"(p), "r"(v) : "memory");
}
__device__ __forceinline__ unsigned ld_acquire_gpu(const unsigned* p) {
    unsigned v;
    asm volatile("ld.acquire.gpu.u32 %0, [%1];" : "=r"(v) : "l"(p) : "memory");
    return v;
}
// packed fp32x2 FMA
__device__ __forceinline__ void F2(unsigned long long &d, unsigned long long a,
                                   unsigned long long b) {
    asm("fma.rn.f32x2 %0, %1, %2, %0;" : "+l"(d) : "l"(a), "l"(b));
}
__device__ __forceinline__ unsigned long long pk2(float x, float y) {
    unsigned long long p;
    asm("mov.b64 %0, {%1, %2};" : "=l"(p) : "f"(x), "f"(y));
    return p;
}
__device__ __forceinline__ float2 upk(unsigned long long v) {
    float2 r;
    asm("mov.b64 {%0, %1}, %2;" : "=f"(r.x), "=f"(r.y) : "l"(v));
    return r;
}

// ---------------------------------------------------------------------------
// Zero initial hidden state + barrier counters (R5 version)
// ---------------------------------------------------------------------------
__global__ void zero_h_kernel() {
    int i = blockIdx.x * blockDim.x + threadIdx.x;
    if (i < 2 * Bsz * Hdim) {
        ((float*)g_h0)[i] = 0.0f;
        ((float*)g_h1)[i] = 0.0f;
    }
    if (i < 8 * 32) g_cnt[i] = 0;
}

// ---------------------------------------------------------------------------
// pre0[t][b][h] = emb[x[b,t]] . W_ih0[h] + b_ih0[h] + b_hh0[h]
// BATCH-MAJOR tiles: block (mt, nc) covers timesteps [t0, t0+64) of ONE
// batch b (mt = b*8 + t0/64). If t0 >= lengths[b], every covered pre0 entry
// is dead (seq epilogue selects hprev for s >= len_b) -> whole CTA exits.
// Alive tiles use the exact R5 pairing/order -> bitwise-identical values.
// ---------------------------------------------------------------------------
__global__ void __launch_bounds__(256) pre0_gemm_kernel(
    const int*   __restrict__ x,
    const float* __restrict__ emb,
    const float* __restrict__ Wih,
    const float* __restrict__ bih,
    const float* __restrict__ bhh,
    const int*   __restrict__ lengths)
{
    __shared__ unsigned long long As2[8][64];
    __shared__ unsigned long long Bs2[8][64];
    __shared__ int tok[64];

    const int mt  = blockIdx.x;            // 0..511
    const int b   = mt >> 3;               // batch 0..63
    const int t0  = (mt & 7) * 64;         // timestep base
    const int ncol = blockIdx.y * 64;
    const int tid  = threadIdx.x;

    if (t0 >= lengths[b]) return;          // fully dead tile

    if (tid < 64) tok[tid] = x[b * Tlen + t0 + tid];   // row r -> t = t0 + r
    __syncthreads();

    const int ty = tid >> 4;
    const int tx = tid & 15;
    const int mm = tid & 63;
    const int kq = tid >> 6;
    const int pm = mm ^ (((mm >> 4) & 1) << 1);

    const int xa  = ((ty >> 2) & 1) << 1;
    const int xb  = ((tx >> 2) & 1) << 1;
    const int ca0 = (ty * 4) ^ xa, ca2 = (ty * 4 + 2) ^ xa;
    const int cb0 = (tx * 4) ^ xb, cb2 = (tx * 4 + 2) ^ xb;

    unsigned long long acc2[4][4];
#pragma unroll
    for (int i = 0; i < 4; i++)
#pragma unroll
        for (int j = 0; j < 4; j++) acc2[i][j] = 0ull;

    for (int kc = 0; kc < Edim; kc += 16) {
        {
            float4 v = *(const float4*)(emb + (size_t)tok[mm] * Edim + kc + kq * 4);
            As2[kq*2+0][pm] = pk2(v.x, v.y);
            As2[kq*2+1][pm] = pk2(v.z, v.w);
            float4 w = *(const float4*)(Wih + (size_t)(ncol + mm) * Edim + kc + kq * 4);
            Bs2[kq*2+0][pm] = pk2(w.x, w.y);
            Bs2[kq*2+1][pm] = pk2(w.z, w.w);
        }
        __syncthreads();
#pragma unroll
        for (int kk2 = 0; kk2 < 8; kk2++) {
            ulonglong2 a01 = *(const ulonglong2*)&As2[kk2][ca0];
            ulonglong2 a23 = *(const ulonglong2*)&As2[kk2][ca2];
            ulonglong2 b01 = *(const ulonglong2*)&Bs2[kk2][cb0];
            ulonglong2 b23 = *(const ulonglong2*)&Bs2[kk2][cb2];
            unsigned long long am[4] = {a01.x, a01.y, a23.x, a23.y};
            unsigned long long bn[4] = {b01.x, b01.y, b23.x, b23.y};
#pragma unroll
            for (int i = 0; i < 4; i++)
#pragma unroll
                for (int j = 0; j < 4; j++) F2(acc2[i][j], am[i], bn[j]);
        }
        __syncthreads();
    }

    const int nbase = ncol + tx * 4;
    float4 bias;
    bias.x = bih[nbase + 0] + bhh[nbase + 0];
    bias.y = bih[nbase + 1] + bhh[nbase + 1];
    bias.z = bih[nbase + 2] + bhh[nbase + 2];
    bias.w = bih[nbase + 3] + bhh[nbase + 3];
#pragma unroll
    for (int i = 0; i < 4; i++) {
        const int t = t0 + ty * 4 + i;     // row -> timestep of batch b
        float2 u0 = upk(acc2[i][0]), u1 = upk(acc2[i][1]);
        float2 u2 = upk(acc2[i][2]), u3 = upk(acc2[i][3]);
        float4 o;
        o.x = u0.x + u0.y + bias.x;  o.y = u1.x + u1.y + bias.y;
        o.z = u2.x + u2.y + bias.z;  o.w = u3.x + u3.y + bias.w;
        *(float4*)(g_pre0 + ((size_t)t * Bsz + b) * Hdim + nbase) = o;
    }
}

// ---------------------------------------------------------------------------
// Per-group barrier: single monotonic counter (reset by zero_h each launch).
// ---------------------------------------------------------------------------
__device__ __forceinline__ void group_barrier(int grp, unsigned need) {
    __syncthreads();
    if (threadIdx.x == 0) {
        atom_add_release_gpu(&g_cnt[grp * 32], 1u);
        while (ld_acquire_gpu(&g_cnt[grp * 32]) < need) { }
    }
    __syncthreads();
}

// f32x2 GEMM phase: 4b x 8h outputs/thread, K-sliced 16 ways.  (R5 exact)
template<int JCOUNT, int WSTRIDE>
__device__ __forceinline__ void phase_accum2(
    const float* __restrict__ hbuf, const float* __restrict__ W,
    int tb, int th, int ks, unsigned long long acc[4][8])
{
#pragma unroll
    for (int bi = 0; bi < 4; bi++)
#pragma unroll
        for (int hi = 0; hi < 8; hi++) acc[bi][hi] = 0ull;

#pragma unroll 4
    for (int j = 0; j < JCOUNT; j++) {
        const int k = ((j * 16 + ks) << 2);
        ulonglong2 a[4], w[8];
#pragma unroll
        for (int q = 0; q < 4; q++)
            a[q] = *(const ulonglong2*)(hbuf + (size_t)(tb + q) * 1024 + k);
#pragma unroll
        for (int q = 0; q < 8; q++)
            w[q] = *(const ulonglong2*)(W + (size_t)(th + q) * WSTRIDE + k);
#pragma unroll
        for (int bi = 0; bi < 4; bi++)
#pragma unroll
            for (int hi = 0; hi < 8; hi++) {
                F2(acc[bi][hi], a[bi].x, w[hi].x);
                F2(acc[bi][hi], a[bi].y, w[hi].y);
            }
    }
}

// 32 partials/lane -> 2 full sums/lane across the 16-lane segment. (R5 exact)
__device__ __forceinline__ void fold32to2(float v[32], int ks) {
    int cnt = 32;
#pragma unroll
    for (int m = 8; m >= 1; m >>= 1) {
        const bool hi = (ks & m) != 0;
        const int half = cnt >> 1;
#pragma unroll
        for (int j = 0; j < 16; j++) {
            if (j >= half) break;
            float send = hi ? v[j] : v[j + half];
            float recv = __shfl_xor_sync(0xffffffffu, send, m, 16);
            float keep = hi ? v[j + half] : v[j];
            v[j] = keep + recv;
        }
        cnt = half;
    }
}

// ---------------------------------------------------------------------------
// Persistent pipelined RNN (exact R5 structure — empirical best).
// 128 CTAs = 8 groups of 16; 128 threads/CTA.
// ---------------------------------------------------------------------------
__global__ void __launch_bounds__(TPB, 1) rnn_seq_kernel(
    const float* __restrict__ Wih,
    const float* __restrict__ Whh,
    const float* __restrict__ bih,
    const float* __restrict__ bhh,
    const int*   __restrict__ lengths,
    float*       __restrict__ out)
{
    extern __shared__ float smem_dyn[];
    float* Wa   = smem_dyn;                 // 32 x 512
    float* Wb   = smem_dyn + 32 * 512;      // 32 x 1024
    float* hbuf = Wb + 32 * 1024;           // 8 x 1024 staging

    const int cta   = blockIdx.x;
    const int grp   = cta >> 4;
    const int bbase = grp * 8;
    const int hbase = (cta & 15) * 32;
    const int tid   = threadIdx.x;

    // resident weight slices
    {
        const float4* src = (const float4*)(Whh + (size_t)hbase * Hdim);
        float4* dst = (float4*)Wa;
        for (int i = tid; i < 32 * Hdim / 4; i += TPB) dst[i] = src[i];

        const float4* s1 = (const float4*)(Wih + (size_t)Hdim * Edim + (size_t)hbase * Edim);
        const float4* s2 = (const float4*)(Whh + (size_t)Hdim * Hdim + (size_t)hbase * Hdim);
        for (int i = tid; i < 32 * 512 / 4; i += TPB) {
            int r = i >> 7, c = i & 127;
            ((float4*)(Wb + (size_t)r * 1024))[c]       = s1[i];
            ((float4*)(Wb + (size_t)r * 1024 + 512))[c] = s2[i];
        }
    }

    // compute mapping: warp halves share th, differ in tb -> 2-way W broadcast
    const int ks = tid & 15;
    const int g  = tid >> 4;
    const int tb = (g & 1) * 4;
    const int th = (g >> 1) * 8;

    // epilogue ownership: lane ks owns outputs o=2ks, 2ks+1
    const int blo = tb + (ks >> 2);
    const int hlo = th + 2 * (ks & 3);
    const int b_o = bbase + blo;
    const int h_o = hbase + hlo;
    const int lenb = lengths[b_o];
    float2 bias1;
    bias1.x = bih[Hdim + h_o] + bhh[Hdim + h_o];
    bias1.y = bih[Hdim + h_o + 1] + bhh[Hdim + h_o + 1];

    // group horizon
    int smax = 1;
#pragma unroll
    for (int q = 0; q < 8; q++) {
        int l = lengths[bbase + q];
        smax = (l > smax) ? l : smax;
    }

    float2 h0fin = make_float2(0.0f, 0.0f);
    float2 h1fin = make_float2(0.0f, 0.0f);

    for (int s = 0; s <= smax; ++s) {
        const int p = s & 1;

        // ---- stage h0_after[s-1] | h1_after[s-2] into smem ----
#pragma unroll
        for (int it = 0; it < 8; it++) {
            int i = tid + it * TPB;
            int r = i >> 7, c = (i & 127) << 2;
            float4 v0 = __ldcg((const float4*)&g_h0[p][bbase + r][c]);
            float4 v1 = __ldcg((const float4*)&g_h1[p][bbase + r][c]);
            *(float4*)(hbuf + (size_t)r * 1024 + c)       = v0;
            *(float4*)(hbuf + (size_t)r * 1024 + 512 + c) = v1;
        }
        // early pre0 load (hidden under GEMM; dead entries never selected)
        float2 preval = make_float2(0.0f, 0.0f);
        if (s < Tlen)
            preval = __ldcs((const float2*)&g_pre0[((size_t)s * Bsz + b_o) * Hdim + h_o]);
        __syncthreads();

        unsigned long long acc2[4][8];
        float v[32];

        // ===== layer 0: h0_new = tanh(pre0 + h0 @ Whh0^T) =====
        if (s < Tlen) {
            phase_accum2<8, 512>(hbuf, Wa, tb, th, ks, acc2);
#pragma unroll
            for (int bi = 0; bi < 4; bi++)
#pragma unroll
                for (int hi = 0; hi < 8; hi++) {
                    float2 u = upk(acc2[bi][hi]);
                    v[bi * 8 + hi] = u.x + u.y;
                }
            fold32to2(v, ks);
            float s0 = v[0] + preval.x;
            float s1 = v[1] + preval.y;
            float2 hp = *(const float2*)&hbuf[(size_t)blo * 1024 + h_o];
            float2 hn;
            hn.x = (s < lenb) ? tanhf(s0) : hp.x;
            hn.y = (s < lenb) ? tanhf(s1) : hp.y;
            *(float2*)&g_h0[p ^ 1][b_o][h_o] = hn;
            h0fin = hn;
        }

        // ===== layer 1: h1_new = tanh([h0_new,h1] @ [Wih1|Whh1]^T + b1) =====
        if (s >= 1) {
            phase_accum2<16, 1024>(hbuf, Wb, tb, th, ks, acc2);
#pragma unroll
            for (int bi = 0; bi < 4; bi++)
#pragma unroll
                for (int hi = 0; hi < 8; hi++) {
                    float2 u = upk(acc2[bi][hi]);
                    v[bi * 8 + hi] = u.x + u.y;
                }
            fold32to2(v, ks);
            float s0 = v[0] + bias1.x;
            float s1 = v[1] + bias1.y;
            float2 hp = *(const float2*)&hbuf[(size_t)blo * 1024 + 512 + h_o];
            float2 hn;
            hn.x = ((s - 1) < lenb) ? tanhf(s0) : hp.x;
            hn.y = ((s - 1) < lenb) ? tanhf(s1) : hp.y;
            if (s < Tlen) *(float2*)&g_h1[p ^ 1][b_o][h_o] = hn;
            h1fin = hn;
        }

        if (s < smax) group_barrier(grp, 16u * (unsigned)(s + 1));
    }

    // outputs: [ h1_final (64x512) | hidden (64x2x512: layer0, layer1) ]
    *(float2*)&out[(size_t)b_o * Hdim + h_o] = h1fin;
    *(float2*)&out[(size_t)Bsz * Hdim + (size_t)b_o * 2 * Hdim + h_o] = h0fin;
    *(float2*)&out[(size_t)Bsz * Hdim + (size_t)b_o * 2 * Hdim + Hdim + h_o] = h1fin;
}

// ---------------------------------------------------------------------------
extern "C" void kernel_launch(void* const* d_in, const int* in_sizes, int n_in,
                              void* d_out, int out_size) {
    const int*   x       = (const int*)  d_in[0];
    const int*   lengths = (const int*)  d_in[1];
    const float* emb     = (const float*)d_in[2];
    const float* Wih     = (const float*)d_in[3];
    const float* Whh     = (const float*)d_in[4];
    const float* bih     = (const float*)d_in[5];
    const float* bhh     = (const float*)d_in[6];
    float* out = (float*)d_out;

    cudaFuncSetAttribute(rnn_seq_kernel,
                         cudaFuncAttributeMaxDynamicSharedMemorySize, SMEM_BYTES);

    zero_h_kernel<<<(2 * Bsz * Hdim + 255) / 256, 256>>>();

    dim3 grid_pre(Tlen, Hdim / 64);   // x: 512 batch-major m-tiles, y: 8 ncols
    pre0_gemm_kernel<<<grid_pre, 256>>>(x, emb, Wih, bih, bhh, lengths);

    rnn_seq_kernel<<<NCTA, TPB, SMEM_BYTES>>>(Wih, Whh, bih, bhh, lengths, out);
}

// round 15
// speedup vs baseline: 2.0438x; 1.0198x over previous
#include <cuda_runtime.h>
#include <math.h>

#define Bsz   64
#define Tlen  512
#define Edim  512
#define Hdim  512
#define NCTA  128
#define TPB   128
// smem: Wa 32*512 + Wb 32*1024 + hbuf 8*1024 floats = 224 KB
#define SMEM_FLOATS (32*512 + 32*1024 + 8*1024)
#define SMEM_BYTES  (SMEM_FLOATS * 4)

__device__ float g_pre0[(size_t)Tlen * Bsz * Hdim];   // [t][b][h]
__device__ float g_h0[2][Bsz][Hdim];
__device__ float g_h1[2][Bsz][Hdim];
__device__ unsigned int g_cnt[8 * 32];   // per-group monotonic barrier counter

// ---------------------------------------------------------------------------
// primitives
// ---------------------------------------------------------------------------
__device__ __forceinline__ void atom_add_release_gpu(unsigned* p, unsigned v) {
    unsigned old;
    asm volatile("atom.add.release.gpu.u32 %0, [%1], %2;"
                 : "=r"(old) : "l"(p), "r"(v) : "memory");
}
__device__ __forceinline__ unsigned ld_acquire_gpu(const unsigned* p) {
    unsigned v;
    asm volatile("ld.acquire.gpu.u32 %0, [%1];" : "=r"(v) : "l"(p) : "memory");
    return v;
}
// packed fp32x2 FMA
__device__ __forceinline__ void F2(unsigned long long &d, unsigned long long a,
                                   unsigned long long b) {
    asm("fma.rn.f32x2 %0, %1, %2, %0;" : "+l"(d) : "l"(a), "l"(b));
}
__device__ __forceinline__ unsigned long long pk2(float x, float y) {
    unsigned long long p;
    asm("mov.b64 %0, {%1, %2};" : "=l"(p) : "f"(x), "f"(y));
    return p;
}
__device__ __forceinline__ float2 upk(unsigned long long v) {
    float2 r;
    asm("mov.b64 {%0, %1}, %2;" : "=f"(r.x), "=f"(r.y) : "l"(v));
    return r;
}

// ---------------------------------------------------------------------------
// Zero initial hidden state + barrier counters
// ---------------------------------------------------------------------------
__global__ void zero_h_kernel() {
    int i = blockIdx.x * blockDim.x + threadIdx.x;
    if (i < 2 * Bsz * Hdim) {
        ((float*)g_h0)[i] = 0.0f;
        ((float*)g_h1)[i] = 0.0f;
    }
    if (i < 8 * 32) g_cnt[i] = 0;
}

// ---------------------------------------------------------------------------
// pre0[t][b][h] = emb[x[b,t]] . W_ih0[h] + b_ih0[h] + b_hh0[h]
// Batch-major tiles with whole-CTA dead-tile skip (R13 winner, unchanged).
// ---------------------------------------------------------------------------
__global__ void __launch_bounds__(256) pre0_gemm_kernel(
    const int*   __restrict__ x,
    const float* __restrict__ emb,
    const float* __restrict__ Wih,
    const float* __restrict__ bih,
    const float* __restrict__ bhh,
    const int*   __restrict__ lengths)
{
    __shared__ unsigned long long As2[8][64];
    __shared__ unsigned long long Bs2[8][64];
    __shared__ int tok[64];

    const int mt  = blockIdx.x;            // 0..511
    const int b   = mt >> 3;               // batch 0..63
    const int t0  = (mt & 7) * 64;         // timestep base
    const int ncol = blockIdx.y * 64;
    const int tid  = threadIdx.x;

    if (t0 >= lengths[b]) return;          // fully dead tile

    if (tid < 64) tok[tid] = x[b * Tlen + t0 + tid];
    __syncthreads();

    const int ty = tid >> 4;
    const int tx = tid & 15;
    const int mm = tid & 63;
    const int kq = tid >> 6;
    const int pm = mm ^ (((mm >> 4) & 1) << 1);

    const int xa  = ((ty >> 2) & 1) << 1;
    const int xb  = ((tx >> 2) & 1) << 1;
    const int ca0 = (ty * 4) ^ xa, ca2 = (ty * 4 + 2) ^ xa;
    const int cb0 = (tx * 4) ^ xb, cb2 = (tx * 4 + 2) ^ xb;

    unsigned long long acc2[4][4];
#pragma unroll
    for (int i = 0; i < 4; i++)
#pragma unroll
        for (int j = 0; j < 4; j++) acc2[i][j] = 0ull;

    for (int kc = 0; kc < Edim; kc += 16) {
        {
            float4 v = *(const float4*)(emb + (size_t)tok[mm] * Edim + kc + kq * 4);
            As2[kq*2+0][pm] = pk2(v.x, v.y);
            As2[kq*2+1][pm] = pk2(v.z, v.w);
            float4 w = *(const float4*)(Wih + (size_t)(ncol + mm) * Edim + kc + kq * 4);
            Bs2[kq*2+0][pm] = pk2(w.x, w.y);
            Bs2[kq*2+1][pm] = pk2(w.z, w.w);
        }
        __syncthreads();
#pragma unroll
        for (int kk2 = 0; kk2 < 8; kk2++) {
            ulonglong2 a01 = *(const ulonglong2*)&As2[kk2][ca0];
            ulonglong2 a23 = *(const ulonglong2*)&As2[kk2][ca2];
            ulonglong2 b01 = *(const ulonglong2*)&Bs2[kk2][cb0];
            ulonglong2 b23 = *(const ulonglong2*)&Bs2[kk2][cb2];
            unsigned long long am[4] = {a01.x, a01.y, a23.x, a23.y};
            unsigned long long bn[4] = {b01.x, b01.y, b23.x, b23.y};
#pragma unroll
            for (int i = 0; i < 4; i++)
#pragma unroll
                for (int j = 0; j < 4; j++) F2(acc2[i][j], am[i], bn[j]);
        }
        __syncthreads();
    }

    const int nbase = ncol + tx * 4;
    float4 bias;
    bias.x = bih[nbase + 0] + bhh[nbase + 0];
    bias.y = bih[nbase + 1] + bhh[nbase + 1];
    bias.z = bih[nbase + 2] + bhh[nbase + 2];
    bias.w = bih[nbase + 3] + bhh[nbase + 3];
#pragma unroll
    for (int i = 0; i < 4; i++) {
        const int t = t0 + ty * 4 + i;
        float2 u0 = upk(acc2[i][0]), u1 = upk(acc2[i][1]);
        float2 u2 = upk(acc2[i][2]), u3 = upk(acc2[i][3]);
        float4 o;
        o.x = u0.x + u0.y + bias.x;  o.y = u1.x + u1.y + bias.y;
        o.z = u2.x + u2.y + bias.z;  o.w = u3.x + u3.y + bias.w;
        *(float4*)(g_pre0 + ((size_t)t * Bsz + b) * Hdim + nbase) = o;
    }
}

// ---------------------------------------------------------------------------
// Per-group barrier: single monotonic counter.
// ---------------------------------------------------------------------------
__device__ __forceinline__ void group_barrier(int grp, unsigned need) {
    __syncthreads();
    if (threadIdx.x == 0) {
        atom_add_release_gpu(&g_cnt[grp * 32], 1u);
        while (ld_acquire_gpu(&g_cnt[grp * 32]) < need) { }
    }
    __syncthreads();
}

// f32x2 GEMM phase: 4b x 8h outputs/thread, K-sliced 16 ways.
// FULL UNROLL: expose all j-iterations to ptxas for cross-j software
// pipelining (loads of j+1.. issued under FMAs of j) — zero traffic cost.
template<int JCOUNT, int WSTRIDE>
__device__ __forceinline__ void phase_accum2(
    const float* __restrict__ hbuf, const float* __restrict__ W,
    int tb, int th, int ks, unsigned long long acc[4][8])
{
#pragma unroll
    for (int bi = 0; bi < 4; bi++)
#pragma unroll
        for (int hi = 0; hi < 8; hi++) acc[bi][hi] = 0ull;

#pragma unroll
    for (int j = 0; j < JCOUNT; j++) {
        const int k = ((j * 16 + ks) << 2);
        ulonglong2 a[4], w[8];
#pragma unroll
        for (int q = 0; q < 4; q++)
            a[q] = *(const ulonglong2*)(hbuf + (size_t)(tb + q) * 1024 + k);
#pragma unroll
        for (int q = 0; q < 8; q++)
            w[q] = *(const ulonglong2*)(W + (size_t)(th + q) * WSTRIDE + k);
#pragma unroll
        for (int bi = 0; bi < 4; bi++)
#pragma unroll
            for (int hi = 0; hi < 8; hi++) {
                F2(acc[bi][hi], a[bi].x, w[hi].x);
                F2(acc[bi][hi], a[bi].y, w[hi].y);
            }
    }
}

// 32 partials/lane -> 2 full sums/lane across the 16-lane segment.
__device__ __forceinline__ void fold32to2(float v[32], int ks) {
    int cnt = 32;
#pragma unroll
    for (int m = 8; m >= 1; m >>= 1) {
        const bool hi = (ks & m) != 0;
        const int half = cnt >> 1;
#pragma unroll
        for (int j = 0; j < 16; j++) {
            if (j >= half) break;
            float send = hi ? v[j] : v[j + half];
            float recv = __shfl_xor_sync(0xffffffffu, send, m, 16);
            float keep = hi ? v[j + half] : v[j];
            v[j] = keep + recv;
        }
        cnt = half;
    }
}

// ---------------------------------------------------------------------------
// Persistent pipelined RNN (R5/R13 structure; only unroll + preval hoist).
// 128 CTAs = 8 groups of 16; 128 threads/CTA.
// ---------------------------------------------------------------------------
__global__ void __launch_bounds__(TPB, 1) rnn_seq_kernel(
    const float* __restrict__ Wih,
    const float* __restrict__ Whh,
    const float* __restrict__ bih,
    const float* __restrict__ bhh,
    const int*   __restrict__ lengths,
    float*       __restrict__ out)
{
    extern __shared__ float smem_dyn[];
    float* Wa   = smem_dyn;                 // 32 x 512
    float* Wb   = smem_dyn + 32 * 512;      // 32 x 1024
    float* hbuf = Wb + 32 * 1024;           // 8 x 1024 staging

    const int cta   = blockIdx.x;
    const int grp   = cta >> 4;
    const int bbase = grp * 8;
    const int hbase = (cta & 15) * 32;
    const int tid   = threadIdx.x;

    // resident weight slices
    {
        const float4* src = (const float4*)(Whh + (size_t)hbase * Hdim);
        float4* dst = (float4*)Wa;
        for (int i = tid; i < 32 * Hdim / 4; i += TPB) dst[i] = src[i];

        const float4* s1 = (const float4*)(Wih + (size_t)Hdim * Edim + (size_t)hbase * Edim);
        const float4* s2 = (const float4*)(Whh + (size_t)Hdim * Hdim + (size_t)hbase * Hdim);
        for (int i = tid; i < 32 * 512 / 4; i += TPB) {
            int r = i >> 7, c = i & 127;
            ((float4*)(Wb + (size_t)r * 1024))[c]       = s1[i];
            ((float4*)(Wb + (size_t)r * 1024 + 512))[c] = s2[i];
        }
    }

    // compute mapping: warp halves share th, differ in tb -> 2-way W broadcast
    const int ks = tid & 15;
    const int g  = tid >> 4;
    const int tb = (g & 1) * 4;
    const int th = (g >> 1) * 8;

    // epilogue ownership: lane ks owns outputs o=2ks, 2ks+1
    const int blo = tb + (ks >> 2);
    const int hlo = th + 2 * (ks & 3);
    const int b_o = bbase + blo;
    const int h_o = hbase + hlo;
    const int lenb = lengths[b_o];
    float2 bias1;
    bias1.x = bih[Hdim + h_o] + bhh[Hdim + h_o];
    bias1.y = bih[Hdim + h_o + 1] + bhh[Hdim + h_o + 1];

    // group horizon
    int smax = 1;
#pragma unroll
    for (int q = 0; q < 8; q++) {
        int l = lengths[bbase + q];
        smax = (l > smax) ? l : smax;
    }

    float2 h0fin = make_float2(0.0f, 0.0f);
    float2 h1fin = make_float2(0.0f, 0.0f);

    for (int s = 0; s <= smax; ++s) {
        const int p = s & 1;

        // early pre0 load — hoisted before staging so it issues first
        float2 preval = make_float2(0.0f, 0.0f);
        if (s < Tlen)
            preval = __ldcs((const float2*)&g_pre0[((size_t)s * Bsz + b_o) * Hdim + h_o]);

        // ---- stage h0_after[s-1] | h1_after[s-2] into smem ----
#pragma unroll
        for (int it = 0; it < 8; it++) {
            int i = tid + it * TPB;
            int r = i >> 7, c = (i & 127) << 2;
            float4 v0 = __ldcg((const float4*)&g_h0[p][bbase + r][c]);
            float4 v1 = __ldcg((const float4*)&g_h1[p][bbase + r][c]);
            *(float4*)(hbuf + (size_t)r * 1024 + c)       = v0;
            *(float4*)(hbuf + (size_t)r * 1024 + 512 + c) = v1;
        }
        __syncthreads();

        unsigned long long acc2[4][8];
        float v[32];

        // ===== layer 0: h0_new = tanh(pre0 + h0 @ Whh0^T) =====
        if (s < Tlen) {
            phase_accum2<8, 512>(hbuf, Wa, tb, th, ks, acc2);
#pragma unroll
            for (int bi = 0; bi < 4; bi++)
#pragma unroll
                for (int hi = 0; hi < 8; hi++) {
                    float2 u = upk(acc2[bi][hi]);
                    v[bi * 8 + hi] = u.x + u.y;
                }
            fold32to2(v, ks);
            float s0 = v[0] + preval.x;
            float s1 = v[1] + preval.y;
            float2 hp = *(const float2*)&hbuf[(size_t)blo * 1024 + h_o];
            float2 hn;
            hn.x = (s < lenb) ? tanhf(s0) : hp.x;
            hn.y = (s < lenb) ? tanhf(s1) : hp.y;
            *(float2*)&g_h0[p ^ 1][b_o][h_o] = hn;
            h0fin = hn;
        }

        // ===== layer 1: h1_new = tanh([h0_new,h1] @ [Wih1|Whh1]^T + b1) =====
        if (s >= 1) {
            phase_accum2<16, 1024>(hbuf, Wb, tb, th, ks, acc2);
#pragma unroll
            for (int bi = 0; bi < 4; bi++)
#pragma unroll
                for (int hi = 0; hi < 8; hi++) {
                    float2 u = upk(acc2[bi][hi]);
                    v[bi * 8 + hi] = u.x + u.y;
                }
            fold32to2(v, ks);
            float s0 = v[0] + bias1.x;
            float s1 = v[1] + bias1.y;
            float2 hp = *(const float2*)&hbuf[(size_t)blo * 1024 + 512 + h_o];
            float2 hn;
            hn.x = ((s - 1) < lenb) ? tanhf(s0) : hp.x;
            hn.y = ((s - 1) < lenb) ? tanhf(s1) : hp.y;
            if (s < Tlen) *(float2*)&g_h1[p ^ 1][b_o][h_o] = hn;
            h1fin = hn;
        }

        if (s < smax) group_barrier(grp, 16u * (unsigned)(s + 1));
    }

    // outputs: [ h1_final (64x512) | hidden (64x2x512: layer0, layer1) ]
    *(float2*)&out[(size_t)b_o * Hdim + h_o] = h1fin;
    *(float2*)&out[(size_t)Bsz * Hdim + (size_t)b_o * 2 * Hdim + h_o] = h0fin;
    *(float2*)&out[(size_t)Bsz * Hdim + (size_t)b_o * 2 * Hdim + Hdim + h_o] = h1fin;
}

// ---------------------------------------------------------------------------
extern "C" void kernel_launch(void* const* d_in, const int* in_sizes, int n_in,
                              void* d_out, int out_size) {
    const int*   x       = (const int*)  d_in[0];
    const int*   lengths = (const int*)  d_in[1];
    const float* emb     = (const float*)d_in[2];
    const float* Wih     = (const float*)d_in[3];
    const float* Whh     = (const float*)d_in[4];
    const float* bih     = (const float*)d_in[5];
    const float* bhh     = (const float*)d_in[6];
    float* out = (float*)d_out;

    cudaFuncSetAttribute(rnn_seq_kernel,
                         cudaFuncAttributeMaxDynamicSharedMemorySize, SMEM_BYTES);

    zero_h_kernel<<<(2 * Bsz * Hdim + 255) / 256, 256>>>();

    dim3 grid_pre(Tlen, Hdim / 64);   // x: 512 batch-major m-tiles, y: 8 ncols
    pre0_gemm_kernel<<<grid_pre, 256>>>(x, emb, Wih, bih, bhh, lengths);

    rnn_seq_kernel<<<NCTA, TPB, SMEM_BYTES>>>(Wih, Whh, bih, bhh, lengths, out);
}